// round 6
// baseline (speedup 1.0000x reference)
#include <cuda_runtime.h>
#include <cuda_bf16.h>
#include <cstdint>

#define DI __device__ __forceinline__

// ---------------------------------------------------------------------------
// Problem:
//   x   : (N=32, C=128, T=512, F=32) fp32
//   out : (N, C, C, F) fp32
//   out[n,i,j,f] = exp(-||x[n,i,:,f]-x[n,j,:,f]||^2 / (2 sigma^2))
//
// R6: k_gram mainloop restructure — CHUNK=128, 3-stage cp.async pipeline with
//     ONE __syncthreads per chunk, ldmatrix.x4 fragment loads.
// ---------------------------------------------------------------------------
#define NB 32
#define CC 128
#define TT 512
#define FF 32

__device__ __nv_bfloat16 g_xb[(size_t)NB * FF * CC * TT];   // 128 MiB
__device__ __nv_bfloat16 g_kt[(size_t)NB * FF * CC * CC];   //  32 MiB

// ---------------------------------------------------------------------------
// Kernel 1: (N,C,T,F) fp32 -> (N,F,C,T) bf16.  Tile 64t x 32f.  (unchanged)
// ---------------------------------------------------------------------------
__global__ void __launch_bounds__(256) k_transpose(const float* __restrict__ x) {
    __shared__ float tile[64][33];
    const int t0 = blockIdx.x * 64;
    const int c  = blockIdx.y;
    const int n  = blockIdx.z;
    const int lane = threadIdx.x;

    const float* src = x + (((size_t)(n * CC + c)) * TT + t0) * FF;
#pragma unroll
    for (int it = 0; it < 8; it++) {
        int t = threadIdx.y + it * 8;
        tile[t][lane] = src[(size_t)t * FF + lane];
    }
    __syncthreads();

#pragma unroll
    for (int it = 0; it < 4; it++) {
        int fi = threadIdx.y + it * 8;
        __nv_bfloat162 v = __floats2bfloat162_rn(tile[2 * lane][fi],
                                                 tile[2 * lane + 1][fi]);
        __nv_bfloat162* dst = reinterpret_cast<__nv_bfloat162*>(
            g_xb + (((size_t)(n * FF + fi)) * CC + c) * TT + t0);
        dst[lane] = v;
    }
}

// ---------------------------------------------------------------------------
// Kernel 2: per-(n,f) 128x128 gram via mma.sync bf16 -> g_kt bf16 coalesced
// grid = 1024 CTAs, block = 256 (8 warps, 2x4 -> warp tile m64 n32)
// CHUNK=128 k-elems (256B/row + 16 pad = 272B stride), 3 stages, 1 sync/chunk
// ---------------------------------------------------------------------------
#define CHUNK      128
#define NCHUNK     4
#define ROW_BYTES  272
#define STAGE_B    (128 * ROW_BYTES)            // 34816
#define SDIAG_OFF  (3 * STAGE_B)                // 104448
#define SMEM_SZ    (SDIAG_OFF + 128 * 4)        // 104960

DI uint32_t smem_u32(const void* p) {
    uint32_t a;
    asm("{ .reg .u64 t; cvta.to.shared.u64 t, %1; cvt.u32.u64 %0, t; }"
        : "=r"(a) : "l"(p));
    return a;
}
DI void cp16(uint32_t saddr, const void* g) {
    asm volatile("cp.async.cg.shared.global [%0], [%1], 16;"
                 :: "r"(saddr), "l"(g) : "memory");
}
DI void cp_commit() { asm volatile("cp.async.commit_group;" ::: "memory"); }
DI void cp_wait_1() { asm volatile("cp.async.wait_group 1;" ::: "memory"); }

DI void ldm_x4(uint32_t& r0, uint32_t& r1, uint32_t& r2, uint32_t& r3,
               uint32_t addr) {
    asm volatile("ldmatrix.sync.aligned.m8n8.x4.shared.b16 {%0,%1,%2,%3}, [%4];"
                 : "=r"(r0), "=r"(r1), "=r"(r2), "=r"(r3) : "r"(addr));
}

DI void mma16816(float& c0, float& c1, float& c2, float& c3,
                 uint32_t a0, uint32_t a1, uint32_t a2, uint32_t a3,
                 uint32_t b0, uint32_t b1) {
    asm volatile(
        "mma.sync.aligned.m16n8k16.row.col.f32.bf16.bf16.f32 "
        "{%0,%1,%2,%3}, {%4,%5,%6,%7}, {%8,%9}, {%0,%1,%2,%3};"
        : "+f"(c0), "+f"(c1), "+f"(c2), "+f"(c3)
        : "r"(a0), "r"(a1), "r"(a2), "r"(a3), "r"(b0), "r"(b1));
}

// load one chunk: rows 0..127, cols [k0, k0+128) bf16 -> padded stage buffer
DI void load_chunk(const __nv_bfloat16* A, uint32_t buf, int tid, int k0) {
    const int row  = tid >> 1;
    const int half = tid & 1;
    const __nv_bfloat16* g = A + (size_t)row * TT + k0 + half * 64;
    const uint32_t s = buf + row * ROW_BYTES + half * 128;
#pragma unroll
    for (int v = 0; v < 8; v++)
        cp16(s + v * 16, g + v * 8);
}

extern "C" __global__ void __launch_bounds__(256, 2)
k_gram(const float* __restrict__ sigma) {
    extern __shared__ char smem[];
    const uint32_t sb = smem_u32(smem);
    const int tid  = threadIdx.x;
    const int wid  = tid >> 5;
    const int lane = tid & 31;
    const int g    = lane >> 2;
    const int c4   = lane & 3;
    const int bid  = blockIdx.x;

    const int RM = (wid >> 2) * 64;
    const int CN = (wid & 3) * 32;

    const __nv_bfloat16* A = g_xb + (size_t)bid * CC * TT;

    // ldmatrix per-thread address offsets (within a stage buffer)
    uint32_t aoff[4], boff[2];
#pragma unroll
    for (int mt = 0; mt < 4; mt++)
        aoff[mt] = (uint32_t)(RM + mt * 16 + (lane & 15)) * ROW_BYTES
                 + ((lane >> 4) << 4);
#pragma unroll
    for (int q = 0; q < 2; q++)
        boff[q] = (uint32_t)(CN + q * 16 + (lane & 7) + ((lane & 16) >> 1))
                      * ROW_BYTES
                 + ((lane & 8) << 1);

    float acc[4][4][4];
#pragma unroll
    for (int mt = 0; mt < 4; mt++)
#pragma unroll
        for (int nt = 0; nt < 4; nt++)
#pragma unroll
            for (int r = 0; r < 4; r++) acc[mt][nt][r] = 0.f;

    // prologue: chunks 0,1 into stages 0,1
    load_chunk(A, sb + 0 * STAGE_B, tid, 0 * CHUNK);
    cp_commit();
    load_chunk(A, sb + 1 * STAGE_B, tid, 1 * CHUNK);
    cp_commit();

#pragma unroll 1
    for (int k = 0; k < NCHUNK; k++) {
        cp_wait_1();              // chunk k resident (newest 1 group may pend)
        __syncthreads();          // all warps: chunk k visible, k-1 consumed

        if (k + 2 < NCHUNK)
            load_chunk(A, sb + ((k + 2) % 3) * STAGE_B, tid, (k + 2) * CHUNK);
        cp_commit();              // (possibly empty) group keeps counts exact

        const uint32_t buf = sb + (k % 3) * STAGE_B;
#pragma unroll
        for (int ks = 0; ks < 8; ks++) {
            const uint32_t kq = ks * 32;
            uint32_t af[4][4];
#pragma unroll
            for (int mt = 0; mt < 4; mt++)
                ldm_x4(af[mt][0], af[mt][1], af[mt][2], af[mt][3],
                       buf + aoff[mt] + kq);
            uint32_t bf[4][2];
#pragma unroll
            for (int q = 0; q < 2; q++)
                ldm_x4(bf[2 * q][0], bf[2 * q][1], bf[2 * q + 1][0],
                       bf[2 * q + 1][1], buf + boff[q] + kq);
#pragma unroll
            for (int mt = 0; mt < 4; mt++)
#pragma unroll
                for (int nt = 0; nt < 4; nt++)
                    mma16816(acc[mt][nt][0], acc[mt][nt][1],
                             acc[mt][nt][2], acc[mt][nt][3],
                             af[mt][0], af[mt][1], af[mt][2], af[mt][3],
                             bf[nt][0], bf[nt][1]);
        }
    }
    __syncthreads();

    // ---- epilogue ----
    float* sdiag = reinterpret_cast<float*>(smem + SDIAG_OFF);

#pragma unroll
    for (int mt = 0; mt < 4; mt++)
#pragma unroll
        for (int nt = 0; nt < 4; nt++)
#pragma unroll
            for (int r = 0; r < 4; r++) {
                const int i = RM + mt * 16 + g + ((r >> 1) << 3);
                const int j = CN + nt * 8 + c4 * 2 + (r & 1);
                if (i == j) sdiag[i] = acc[mt][nt][r];
            }
    __syncthreads();

    const float sg   = sigma[0];
    const float ninv = -0.5f / (sg * sg);

    float dj[4][2];
#pragma unroll
    for (int nt = 0; nt < 4; nt++) {
        dj[nt][0] = sdiag[CN + nt * 8 + c4 * 2];
        dj[nt][1] = sdiag[CN + nt * 8 + c4 * 2 + 1];
    }

    // coalesced bf16 stores: g_kt[(n,f), i, j]  (values are exact 0.0 / 1.0)
    __nv_bfloat16* kt = g_kt + ((size_t)bid << 14);
#pragma unroll
    for (int mt = 0; mt < 4; mt++) {
#pragma unroll
        for (int rh = 0; rh < 2; rh++) {
            const int i  = RM + mt * 16 + g + rh * 8;
            const float di = sdiag[i];
            __nv_bfloat16* row = kt + ((size_t)i << 7);
#pragma unroll
            for (int nt = 0; nt < 4; nt++) {
                const int j0 = CN + nt * 8 + c4 * 2;
                const float g0 = acc[mt][nt][rh * 2 + 0];
                const float g1 = acc[mt][nt][rh * 2 + 1];
                const float a0 = fmaxf(di + dj[nt][0] - 2.0f * g0, 0.0f) * ninv;
                const float a1 = fmaxf(di + dj[nt][1] - 2.0f * g1, 0.0f) * ninv;
                float v0 = 0.0f, v1 = 0.0f;
                if (a0 > -105.0f) v0 = __expf(a0);   // exp underflows to 0 below
                if (a1 > -105.0f) v1 = __expf(a1);
                *reinterpret_cast<__nv_bfloat162*>(row + j0) =
                    __floats2bfloat162_rn(v0, v1);
            }
        }
    }
}

// ---------------------------------------------------------------------------
// Kernel 3: g_kt bf16 (N, F, M=C*C) -> out f32 (N, M, F)   (unchanged)
// ---------------------------------------------------------------------------
__global__ void __launch_bounds__(256) k_otr(float* __restrict__ out) {
    __shared__ __nv_bfloat162 tile[32][33];
    const int m0 = blockIdx.x * 64;
    const int n  = blockIdx.y;
    const int lane = threadIdx.x;

    const __nv_bfloat162* src = reinterpret_cast<const __nv_bfloat162*>(
        g_kt + ((size_t)n << 19));
#pragma unroll
    for (int it = 0; it < 4; it++) {
        int fi = threadIdx.y + it * 8;
        tile[fi][lane] = src[((size_t)fi << 13) + (m0 >> 1) + lane];
    }
    __syncthreads();

    float* dst = out + ((size_t)n << 19);
#pragma unroll
    for (int it = 0; it < 8; it++) {
        int mi = threadIdx.y + it * 8;
        __nv_bfloat162 p = tile[lane][mi >> 1];
        float v = (mi & 1) ? __bfloat162float(__high2bfloat16(p))
                           : __bfloat162float(__low2bfloat16(p));
        dst[(size_t)(m0 + mi) * FF + lane] = v;
    }
}

// ---------------------------------------------------------------------------
// launch
// ---------------------------------------------------------------------------
extern "C" void kernel_launch(void* const* d_in, const int* in_sizes, int n_in,
                              void* d_out, int out_size) {
    const float* x     = (const float*)d_in[0];
    const float* sigma = (const float*)d_in[1];
    float* out         = (float*)d_out;
    (void)in_sizes; (void)n_in; (void)out_size;

    dim3 g1(TT / 64, CC, NB), b1(32, 8);
    k_transpose<<<g1, b1>>>(x);

    cudaFuncSetAttribute(k_gram, cudaFuncAttributeMaxDynamicSharedMemorySize, SMEM_SZ);
    k_gram<<<NB * FF, 256, SMEM_SZ>>>(sigma);

    dim3 g3(CC * CC / 64, NB), b3(32, 8);
    k_otr<<<g3, b3>>>(out);
}

// round 7
// speedup vs baseline: 1.0469x; 1.0469x over previous
#include <cuda_runtime.h>
#include <cuda_bf16.h>
#include <cstdint>

#define DI __device__ __forceinline__

// ---------------------------------------------------------------------------
// Problem:
//   x   : (N=32, C=128, T=512, F=32) fp32
//   out : (N, C, C, F) fp32
//   out[n,i,j,f] = exp(-||x[n,i,:,f]-x[n,j,:,f]||^2 / (2 sigma^2))
//
// R7: k1 rewritten (LDG.128 reads, skewed smem, STG.64 bf16x4 writes);
//     k_gram = R5-proven mainloop + 3rd pipeline stage (wait_group 2);
//     k_otr unchanged.
// ---------------------------------------------------------------------------
#define NB 32
#define CC 128
#define TT 512
#define FF 32

__device__ __nv_bfloat16 g_xb[(size_t)NB * FF * CC * TT];   // 128 MiB
__device__ __nv_bfloat16 g_kt[(size_t)NB * FF * CC * CC];   //  32 MiB

// ---------------------------------------------------------------------------
// Kernel 1: (N,C,T,F) fp32 -> (N,F,C,T) bf16.  Tile 64t x 32f.
// grid (T/64=8, C, N), block 256.
// smem tile[t][(f+t)&31] skew: STS conflict-free, LDS 2-way.
// ---------------------------------------------------------------------------
__global__ void __launch_bounds__(256) k_transpose(const float* __restrict__ x) {
    __shared__ float tile[64][32];
    const int t0  = blockIdx.x * 64;
    const int c   = blockIdx.y;
    const int n   = blockIdx.z;
    const int tid = threadIdx.x;

    const float* src = x + (((size_t)(n * CC + c)) * TT + t0) * FF;

    // read: 2 x LDG.128 per thread (rows 32/iter: tid/8 = row, tid%8 = f-quad)
#pragma unroll
    for (int it = 0; it < 2; it++) {
        const int t  = it * 32 + (tid >> 3);
        const int f4 = (tid & 7) * 4;
        const float4 v = *reinterpret_cast<const float4*>(src + (size_t)t * FF + f4);
        tile[t][(f4 + 0 + t) & 31] = v.x;
        tile[t][(f4 + 1 + t) & 31] = v.y;
        tile[t][(f4 + 2 + t) & 31] = v.z;
        tile[t][(f4 + 3 + t) & 31] = v.w;
    }
    __syncthreads();

    // write: each thread packs 4 consecutive t of one f -> STG.64
    // thread -> (f = tid/8? ) use: f = tid >> 3  (0..31), tq = tid & 7 (0..7)
    const int f  = tid >> 3;
    const int tq = (tid & 7) * 8;       // 8 t per thread? no: 64t/8thr = 8 t
    __nv_bfloat16* dst = g_xb + (((size_t)(n * FF + f)) * CC + c) * TT + t0 + tq;
#pragma unroll
    for (int h = 0; h < 2; h++) {       // two bf16x4 stores (8 t total)
        const int tb = tq + h * 4;
        float a0 = tile[tb + 0][(f + tb + 0) & 31];
        float a1 = tile[tb + 1][(f + tb + 1) & 31];
        float a2 = tile[tb + 2][(f + tb + 2) & 31];
        float a3 = tile[tb + 3][(f + tb + 3) & 31];
        __nv_bfloat162 p0 = __floats2bfloat162_rn(a0, a1);
        __nv_bfloat162 p1 = __floats2bfloat162_rn(a2, a3);
        uint2 pk = make_uint2(*reinterpret_cast<uint32_t*>(&p0),
                              *reinterpret_cast<uint32_t*>(&p1));
        *reinterpret_cast<uint2*>(dst + h * 4) = pk;
    }
}

// ---------------------------------------------------------------------------
// Kernel 2: per-(n,f) 128x128 gram via mma.sync bf16 -> g_kt bf16 coalesced
// grid = 1024, block = 256 (8 warps, 2x4 -> warp tile m64 n32)
// R5 mainloop + 3 stages (prefetch distance 2, wait_group 2, always-commit)
// ---------------------------------------------------------------------------
#define CHUNK      64
#define NCHUNK     8
#define ROW_BYTES  144           // 64 bf16 data + 8 pad  (conflict-free frags)
#define STAGE_B    (128 * ROW_BYTES)        // 18432
#define SDIAG_OFF  (3 * STAGE_B)            // 55296
#define SMEM_SZ    (SDIAG_OFF + 128 * 4)    // 55808

DI void cp16(void* saddr, const void* g) {
    uint32_t a;
    asm("{ .reg .u64 t; cvta.to.shared.u64 t, %1; cvt.u32.u64 %0, t; }"
        : "=r"(a) : "l"(saddr));
    asm volatile("cp.async.cg.shared.global [%0], [%1], 16;"
                 :: "r"(a), "l"(g) : "memory");
}
DI void cp_commit() { asm volatile("cp.async.commit_group;" ::: "memory"); }
DI void cp_wait_2() { asm volatile("cp.async.wait_group 2;" ::: "memory"); }

DI void mma16816(float& c0, float& c1, float& c2, float& c3,
                 uint32_t a0, uint32_t a1, uint32_t a2, uint32_t a3,
                 uint32_t b0, uint32_t b1) {
    asm volatile(
        "mma.sync.aligned.m16n8k16.row.col.f32.bf16.bf16.f32 "
        "{%0,%1,%2,%3}, {%4,%5,%6,%7}, {%8,%9}, {%0,%1,%2,%3};"
        : "+f"(c0), "+f"(c1), "+f"(c2), "+f"(c3)
        : "r"(a0), "r"(a1), "r"(a2), "r"(a3), "r"(b0), "r"(b1));
}

DI void load_chunk(const __nv_bfloat16* A, char* buf, int tid, int k0) {
    const int row  = tid >> 1;
    const int half = tid & 1;
    const __nv_bfloat16* g = A + (size_t)row * TT + k0 + half * 32;
    char* s = buf + row * ROW_BYTES + half * 64;
#pragma unroll
    for (int v = 0; v < 4; v++)
        cp16(s + v * 16, g + v * 8);
}

extern "C" __global__ void __launch_bounds__(256, 2)
k_gram(const float* __restrict__ sigma) {
    extern __shared__ char smem[];
    const int tid  = threadIdx.x;
    const int wid  = tid >> 5;
    const int lane = tid & 31;
    const int g    = lane >> 2;
    const int c4   = lane & 3;
    const int bid  = blockIdx.x;

    const int RM = (wid >> 2) * 64;
    const int CN = (wid & 3) * 32;

    const __nv_bfloat16* A = g_xb + (size_t)bid * CC * TT;

    float acc[4][4][4];
#pragma unroll
    for (int mt = 0; mt < 4; mt++)
#pragma unroll
        for (int nt = 0; nt < 4; nt++)
#pragma unroll
            for (int r = 0; r < 4; r++) acc[mt][nt][r] = 0.f;

    // prologue: chunks 0,1 -> stages 0,1
    load_chunk(A, smem + 0 * STAGE_B, tid, 0 * CHUNK);
    cp_commit();
    load_chunk(A, smem + 1 * STAGE_B, tid, 1 * CHUNK);
    cp_commit();

#pragma unroll 1
    for (int k = 0; k < NCHUNK; k++) {
        if (k + 2 < NCHUNK)
            load_chunk(A, smem + ((k + 2) % 3) * STAGE_B, tid, (k + 2) * CHUNK);
        cp_commit();              // empty group fine; keeps wait count exact
        cp_wait_2();              // chunk k resident
        __syncthreads();

        const char* buf = smem + (k % 3) * STAGE_B;
#pragma unroll
        for (int ks = 0; ks < 4; ks++) {
            const int kb = ks * 16 + c4 * 2;
            uint32_t af[4][4];
#pragma unroll
            for (int mt = 0; mt < 4; mt++) {
                const char* r0 = buf + (RM + mt * 16 + g) * ROW_BYTES;
                af[mt][0] = *(const uint32_t*)(r0 + kb * 2);
                af[mt][1] = *(const uint32_t*)(r0 + 8 * ROW_BYTES + kb * 2);
                af[mt][2] = *(const uint32_t*)(r0 + (kb + 8) * 2);
                af[mt][3] = *(const uint32_t*)(r0 + 8 * ROW_BYTES + (kb + 8) * 2);
            }
            uint32_t bf[4][2];
#pragma unroll
            for (int nt = 0; nt < 4; nt++) {
                const char* r0 = buf + (CN + nt * 8 + g) * ROW_BYTES;
                bf[nt][0] = *(const uint32_t*)(r0 + kb * 2);
                bf[nt][1] = *(const uint32_t*)(r0 + (kb + 8) * 2);
            }
#pragma unroll
            for (int mt = 0; mt < 4; mt++)
#pragma unroll
                for (int nt = 0; nt < 4; nt++)
                    mma16816(acc[mt][nt][0], acc[mt][nt][1],
                             acc[mt][nt][2], acc[mt][nt][3],
                             af[mt][0], af[mt][1], af[mt][2], af[mt][3],
                             bf[nt][0], bf[nt][1]);
        }
        __syncthreads();          // buffer-reuse safety (stage (k+2)%3 == (k-1)%3)
    }

    // ---- epilogue ----
    float* sdiag = reinterpret_cast<float*>(smem + SDIAG_OFF);

#pragma unroll
    for (int mt = 0; mt < 4; mt++)
#pragma unroll
        for (int nt = 0; nt < 4; nt++)
#pragma unroll
            for (int r = 0; r < 4; r++) {
                const int i = RM + mt * 16 + g + ((r >> 1) << 3);
                const int j = CN + nt * 8 + c4 * 2 + (r & 1);
                if (i == j) sdiag[i] = acc[mt][nt][r];
            }
    __syncthreads();

    const float sg   = sigma[0];
    const float ninv = -0.5f / (sg * sg);

    float dj[4][2];
#pragma unroll
    for (int nt = 0; nt < 4; nt++) {
        dj[nt][0] = sdiag[CN + nt * 8 + c4 * 2];
        dj[nt][1] = sdiag[CN + nt * 8 + c4 * 2 + 1];
    }

    __nv_bfloat16* kt = g_kt + ((size_t)bid << 14);
#pragma unroll
    for (int mt = 0; mt < 4; mt++) {
#pragma unroll
        for (int rh = 0; rh < 2; rh++) {
            const int i  = RM + mt * 16 + g + rh * 8;
            const float di = sdiag[i];
            __nv_bfloat16* row = kt + ((size_t)i << 7);
#pragma unroll
            for (int nt = 0; nt < 4; nt++) {
                const int j0 = CN + nt * 8 + c4 * 2;
                const float g0 = acc[mt][nt][rh * 2 + 0];
                const float g1 = acc[mt][nt][rh * 2 + 1];
                const float a0 = fmaxf(di + dj[nt][0] - 2.0f * g0, 0.0f) * ninv;
                const float a1 = fmaxf(di + dj[nt][1] - 2.0f * g1, 0.0f) * ninv;
                float v0 = 0.0f, v1 = 0.0f;
                if (a0 > -105.0f) v0 = __expf(a0);   // underflow -> exact 0
                if (a1 > -105.0f) v1 = __expf(a1);
                *reinterpret_cast<__nv_bfloat162*>(row + j0) =
                    __floats2bfloat162_rn(v0, v1);
            }
        }
    }
}

// ---------------------------------------------------------------------------
// Kernel 3: g_kt bf16 (N, F, M=C*C) -> out f32 (N, M, F)   (unchanged)
// ---------------------------------------------------------------------------
__global__ void __launch_bounds__(256) k_otr(float* __restrict__ out) {
    __shared__ __nv_bfloat162 tile[32][33];
    const int m0 = blockIdx.x * 64;
    const int n  = blockIdx.y;
    const int lane = threadIdx.x;

    const __nv_bfloat162* src = reinterpret_cast<const __nv_bfloat162*>(
        g_kt + ((size_t)n << 19));
#pragma unroll
    for (int it = 0; it < 4; it++) {
        int fi = threadIdx.y + it * 8;
        tile[fi][lane] = src[((size_t)fi << 13) + (m0 >> 1) + lane];
    }
    __syncthreads();

    float* dst = out + ((size_t)n << 19);
#pragma unroll
    for (int it = 0; it < 8; it++) {
        int mi = threadIdx.y + it * 8;
        __nv_bfloat162 p = tile[lane][mi >> 1];
        float v = (mi & 1) ? __bfloat162float(__high2bfloat16(p))
                           : __bfloat162float(__low2bfloat16(p));
        dst[(size_t)(m0 + mi) * FF + lane] = v;
    }
}

// ---------------------------------------------------------------------------
// launch
// ---------------------------------------------------------------------------
extern "C" void kernel_launch(void* const* d_in, const int* in_sizes, int n_in,
                              void* d_out, int out_size) {
    const float* x     = (const float*)d_in[0];
    const float* sigma = (const float*)d_in[1];
    float* out         = (float*)d_out;
    (void)in_sizes; (void)n_in; (void)out_size;

    dim3 g1(TT / 64, CC, NB);
    k_transpose<<<g1, 256>>>(x);

    cudaFuncSetAttribute(k_gram, cudaFuncAttributeMaxDynamicSharedMemorySize, SMEM_SZ);
    k_gram<<<NB * FF, 256, SMEM_SZ>>>(sigma);

    dim3 g3(CC * CC / 64, NB), b3(32, 8);
    k_otr<<<g3, b3>>>(out);
}